// round 13
// baseline (speedup 1.0000x reference)
#include <cuda_runtime.h>
#include <cuda_bf16.h>
#include <math.h>
#include <stdint.h>

#define DIM    768
#define DSTATE 16
#define DCONV  4
#define EE     1536          // expand dim
#define BB     2
#define LL     2048
#define BL     (BB*LL)       // 4096
#define EPS    1e-6f

#define CH     32            // chunk length
#define NCH    (LL/CH)       // 64 chunks

// ---------------- scratch (static device arrays; no allocations) -------------
__device__ float          g_xp  [BL * EE];              // after in-proj (fp32)
__device__ __nv_bfloat16  g_xnh [BL * DIM];             // rmsnorm out hi
__device__ __nv_bfloat16  g_xnl [BL * DIM];             // rmsnorm out lo
__device__ __nv_bfloat16  g_winh[EE * DIM];
__device__ __nv_bfloat16  g_winl[EE * DIM];
__device__ __nv_bfloat16  g_wouth[DIM * EE];
__device__ __nv_bfloat16  g_woutl[DIM * EE];
__device__ __nv_bfloat16  g_yh  [BL * EE];              // final scan out hi
__device__ __nv_bfloat16  g_yl  [BL * EE];              // final scan out lo

__device__ __forceinline__ float sigmoidf_(float v) {
    return 1.0f / (1.0f + expf(-v));
}

__device__ __forceinline__ uint32_t smem_u32_(const void* p) {
    uint32_t a;
    asm("{ .reg .u64 t; cvta.to.shared.u64 t, %1; cvt.u32.u64 %0, t; }"
        : "=r"(a) : "l"(p));
    return a;
}

// ---------------- rmsnorm (writes bf16 hi/lo split) --------------------------
__global__ void rmsnorm_kernel(const float* __restrict__ x,
                               const float* __restrict__ gamma,
                               __nv_bfloat16* __restrict__ xnh,
                               __nv_bfloat16* __restrict__ xnl)
{
    const int row = blockIdx.x;
    const float* xr = x + (size_t)row * DIM;

    float v0 = xr[threadIdx.x];
    float v1 = xr[threadIdx.x + 256];
    float v2 = xr[threadIdx.x + 512];
    float ss = v0 * v0 + v1 * v1 + v2 * v2;

    #pragma unroll
    for (int o = 16; o > 0; o >>= 1)
        ss += __shfl_xor_sync(0xffffffffu, ss, o);

    __shared__ float warp_s[8];
    int wid = threadIdx.x >> 5, lane = threadIdx.x & 31;
    if (lane == 0) warp_s[wid] = ss;
    __syncthreads();
    if (wid == 0) {
        float t = (lane < 8) ? warp_s[lane] : 0.f;
        #pragma unroll
        for (int o = 4; o > 0; o >>= 1)
            t += __shfl_xor_sync(0xffffffffu, t, o);
        if (lane == 0) warp_s[0] = t;
    }
    __syncthreads();
    float rms = sqrtf(warp_s[0] * (1.0f / DIM));
    float inv = 1.0f / (rms + EPS);

    #pragma unroll
    for (int k = 0; k < 3; k++) {
        int i = threadIdx.x + k * 256;
        float v = (k == 0) ? v0 : (k == 1) ? v1 : v2;
        float o = gamma[i] * v * inv;
        __nv_bfloat16 h = __float2bfloat16(o);
        xnh[(size_t)row * DIM + i] = h;
        xnl[(size_t)row * DIM + i] = __float2bfloat16(o - __bfloat162float(h));
    }
}

// ---------------- weight conversion fp32 -> bf16 hi/lo -----------------------
__global__ void convert_w_kernel(const float* __restrict__ W_in,
                                 const float* __restrict__ W_out,
                                 __nv_bfloat16* __restrict__ winh,
                                 __nv_bfloat16* __restrict__ winl,
                                 __nv_bfloat16* __restrict__ wouth,
                                 __nv_bfloat16* __restrict__ woutl)
{
    const int SZ = EE * DIM;
    int idx = blockIdx.x * blockDim.x + threadIdx.x;
    if (idx >= 2 * SZ) return;
    const float* s; __nv_bfloat16 *dh, *dl; int j;
    if (idx < SZ) { s = W_in;  j = idx;      dh = winh;  dl = winl;  }
    else          { s = W_out; j = idx - SZ; dh = wouth; dl = woutl; }
    float v = s[j];
    __nv_bfloat16 h = __float2bfloat16(v);
    dh[j] = h;
    dl[j] = __float2bfloat16(v - __bfloat162float(h));
}

// ======================= HMMA (mma.sync) GEMM ================================
// (unchanged from round 12 — passing)
#define BKT   32
#define PADR  40
#define PLANE (128 * PADR)
#define STAGE (4 * PLANE)
#define SMEM_GEMM (2 * STAGE * 2)      // 81920 bytes

__device__ __forceinline__ void mma16816(float* d, const uint32_t* a, const uint32_t* b) {
    asm volatile(
        "mma.sync.aligned.m16n8k16.row.col.f32.bf16.bf16.f32 "
        "{%0,%1,%2,%3}, {%4,%5,%6,%7}, {%8,%9}, {%0,%1,%2,%3};"
        : "+f"(d[0]), "+f"(d[1]), "+f"(d[2]), "+f"(d[3])
        : "r"(a[0]), "r"(a[1]), "r"(a[2]), "r"(a[3]), "r"(b[0]), "r"(b[1]));
}

__device__ __forceinline__ void ldsm4(uint32_t* r, uint32_t addr) {
    asm volatile("ldmatrix.sync.aligned.m8n8.x4.shared.b16 {%0,%1,%2,%3}, [%4];"
                 : "=r"(r[0]), "=r"(r[1]), "=r"(r[2]), "=r"(r[3]) : "r"(addr));
}

#define CP_ASYNC16(s, g) asm volatile("cp.async.cg.shared.global [%0], [%1], 16;" :: "r"(s), "l"(g))
#define CP_COMMIT()      asm volatile("cp.async.commit_group;")
#define CP_WAIT1()       asm volatile("cp.async.wait_group 1;")

template<bool RESID>
__global__ __launch_bounds__(256, 2)
void gemm_mma_kernel(const __nv_bfloat16* __restrict__ Ah,
                     const __nv_bfloat16* __restrict__ Al,
                     const __nv_bfloat16* __restrict__ Bh,
                     const __nv_bfloat16* __restrict__ Bl,
                     const float* __restrict__ bias,
                     const float* __restrict__ resid,
                     float* __restrict__ Cout,
                     int N, int K)
{
    extern __shared__ __nv_bfloat16 sm[];
    const uint32_t sm32 = smem_u32_(sm);
    const int tid  = threadIdx.x;
    const int wid  = tid >> 5, lane = tid & 31;
    const int g    = lane >> 2;
    const int t2   = (lane & 3) * 2;
    const int brow = blockIdx.y * 128, bcol = blockIdx.x * 128;
    const int warp_m = (wid >> 2) * 64;
    const int warp_n = (wid & 3) * 32;

    const __nv_bfloat16* gptr[4] = { Ah, Al, Bh, Bl };

    const int arow  = (lane & 7) + 8 * ((lane >> 3) & 1);
    const int akofs = 8 * (lane >> 4);
    const uint32_t a_off = (uint32_t)((warp_m + arow) * PADR + akofs) * 2;
    const int browl = (lane & 7) + 8 * (lane >> 4);
    const int bkofs = 8 * ((lane >> 3) & 1);
    const uint32_t b_off = (uint32_t)((warp_n + browl) * PADR + bkofs) * 2;

    float acc[4][4][4];
    #pragma unroll
    for (int mt = 0; mt < 4; mt++)
        #pragma unroll
        for (int nt = 0; nt < 4; nt++)
            #pragma unroll
            for (int q = 0; q < 4; q++) acc[mt][nt][q] = 0.f;

    auto issue = [&](int st, int kt) {
        uint32_t sb = sm32 + (uint32_t)st * STAGE * 2;
        #pragma unroll
        for (int q = 0; q < 8; q++) {
            int ch = tid + q * 256;
            int p  = ch >> 9;
            int rc = ch & 511;
            int r  = rc >> 2;
            int c  = (rc & 3) * 8;
            int rbase = (p < 2) ? brow : bcol;
            uint32_t sa = sb + (uint32_t)(p * PLANE + r * PADR + c) * 2;
            const __nv_bfloat16* ga = gptr[p] + (size_t)(rbase + r) * K + kt + c;
            CP_ASYNC16(sa, ga);
        }
        CP_COMMIT();
    };

    const int NK = K / BKT;
    issue(0, 0);
    issue(1, BKT);
    CP_WAIT1();
    __syncthreads();

    for (int i = 0; i < NK; i++) {
        const int st = i & 1;
        const uint32_t sbase = sm32 + (uint32_t)st * STAGE * 2;

        #pragma unroll
        for (int kk = 0; kk < BKT; kk += 16) {
            const uint32_t kb = (uint32_t)kk * 2;
            uint32_t ah[4][4], al[4][4], bh[2][4], bl[2][4];
            #pragma unroll
            for (int mt = 0; mt < 4; mt++) {
                uint32_t ad = sbase + a_off + (uint32_t)(mt * 16 * PADR) * 2 + kb;
                ldsm4(ah[mt], ad);
                ldsm4(al[mt], ad + (uint32_t)PLANE * 2);
            }
            #pragma unroll
            for (int ntp = 0; ntp < 2; ntp++) {
                uint32_t bd = sbase + b_off + (uint32_t)((2 * PLANE) + ntp * 16 * PADR) * 2 + kb;
                ldsm4(bh[ntp], bd);
                ldsm4(bl[ntp], bd + (uint32_t)PLANE * 2);
            }

            #pragma unroll
            for (int mt = 0; mt < 4; mt++)
                #pragma unroll
                for (int nt = 0; nt < 4; nt++) {
                    const uint32_t* fh = &bh[nt >> 1][(nt & 1) * 2];
                    const uint32_t* fl = &bl[nt >> 1][(nt & 1) * 2];
                    mma16816(acc[mt][nt], ah[mt], fh);
                    mma16816(acc[mt][nt], ah[mt], fl);
                    mma16816(acc[mt][nt], al[mt], fh);
                }
        }

        __syncthreads();
        if (i + 2 < NK) issue(st, (i + 2) * BKT);
        else            CP_COMMIT();
        CP_WAIT1();
        __syncthreads();
    }

    #pragma unroll
    for (int mt = 0; mt < 4; mt++) {
        int r0 = brow + warp_m + mt * 16 + g;
        #pragma unroll
        for (int nt = 0; nt < 4; nt++) {
            int c = bcol + warp_n + nt * 8 + t2;
            float2 bv = *(const float2*)&bias[c];
            float2 o0, o1;
            o0.x = acc[mt][nt][0] + bv.x;
            o0.y = acc[mt][nt][1] + bv.y;
            o1.x = acc[mt][nt][2] + bv.x;
            o1.y = acc[mt][nt][3] + bv.y;
            if (RESID) {
                float2 rv0 = *(const float2*)&resid[(size_t)r0 * N + c];
                float2 rv1 = *(const float2*)&resid[(size_t)(r0 + 8) * N + c];
                o0.x += rv0.x; o0.y += rv0.y;
                o1.x += rv1.x; o1.y += rv1.y;
            }
            *(float2*)&Cout[(size_t)r0 * N + c]       = o0;
            *(float2*)&Cout[(size_t)(r0 + 8) * N + c] = o1;
        }
    }
}

// ================= fused scan: local scan + combine + output =================
// One block = (b, 4 consecutive e). 256 threads = (e_local 0..3) x (chunk 0..63).
// smem: xs = block's xp slice (XOR-swizzled), gs = per-chunk g states (pad 17).
#define GEB     4
#define EPB     (EE / GEB)            // 384 blocks per batch
#define XS_RS   2052                  // floats per e-row (2048 + 4 pad)
#define GS_CS   17                    // floats per (el, c) record (16 + 1 pad)
#define SMEM_SCAN ((GEB * XS_RS + GEB * NCH * GS_CS) * 4)   // 50240 bytes

__global__ __launch_bounds__(256)
void scan_fused_kernel(const float* __restrict__ xp,
                       const float* __restrict__ A,
                       const float* __restrict__ Bp,
                       const float* __restrict__ C,
                       const float* __restrict__ convw,
                       __nv_bfloat16* __restrict__ yh,
                       __nv_bfloat16* __restrict__ yl)
{
    extern __shared__ float sf[];
    float* xs = sf;                      // GEB * XS_RS
    float* gs = sf + GEB * XS_RS;        // GEB * NCH * GS_CS

    const int b  = blockIdx.x / EPB;
    const int e0 = (blockIdx.x % EPB) * GEB;
    const int tid = threadIdx.x;

    // ---- load xp slice into smem (swizzle p = t ^ ((t>>5)&31)) ----
    {
        int lel = tid & 3;               // e_local
        int tb  = tid >> 2;              // 0..63
        const float* gp = xp + (size_t)b * LL * EE + e0 + lel;
        #pragma unroll 8
        for (int it = 0; it < 32; it++) {
            int t = tb + it * 64;
            int p = t ^ ((t >> 5) & 31);
            xs[lel * XS_RS + p] = gp[(size_t)t * EE];
        }
    }
    __syncthreads();

    const int el = tid >> 6;             // 0..3
    const int c  = tid & 63;             // chunk
    const int e  = e0 + el;
    const float* xrow = xs + el * XS_RS;

    float sA[DSTATE], g[DSTATE];
    #pragma unroll
    for (int n = 0; n < DSTATE; n++) {
        sA[n] = sigmoidf_(A[e * DSTATE + n]);
        g[n] = 0.f;
    }
    const float w0 = convw[e * 4 + 0];
    const float w1 = convw[e * 4 + 1];
    const float w2 = convw[e * 4 + 2];
    const float w3 = convw[e * 4 + 3];

    const int t0 = c * CH;
    float xm1 = (c > 0) ? xrow[(t0 - 1) ^ (((t0 - 1) >> 5) & 31)] : 0.f;
    float xm2 = (c > 0) ? xrow[(t0 - 2) ^ (((t0 - 2) >> 5) & 31)] : 0.f;
    float xm3 = (c > 0) ? xrow[(t0 - 3) ^ (((t0 - 3) >> 5) & 31)] : 0.f;
    const float xm1s = xm1, xm2s = xm2, xm3s = xm3;   // saved for phase 3

    const int sw = c & 31;               // swizzle key (t>>5 == c for in-chunk t)

    // ---- phase 1: local g-scan of own chunk ----
    #pragma unroll 8
    for (int j = 0; j < CH; j++) {
        float xv = xrow[t0 + (j ^ sw)];
        float xcv = xv * w3 + xm1 * w2 + xm2 * w1 + xm3 * w0;
        xm3 = xm2; xm2 = xm1; xm1 = xv;
        #pragma unroll
        for (int n = 0; n < DSTATE; n++)
            g[n] = fmaf(sA[n], g[n], xcv);
    }
    {
        float* gp = gs + (el * NCH + c) * GS_CS;
        #pragma unroll
        for (int n = 0; n < DSTATE; n++) gp[n] = g[n];
    }
    __syncthreads();

    // ---- phase 2: sequential combine across chunks (in place) ----
    if (tid < GEB * DSTATE) {
        int el2 = tid >> 4;              // 0..3
        int n2  = tid & 15;
        float a2 = sigmoidf_(A[(e0 + el2) * DSTATE + n2]);
        float pw = a2;
        #pragma unroll
        for (int i = 0; i < 5; i++) pw *= pw;   // sA^32
        float* base = gs + el2 * NCH * GS_CS + n2;
        float h = 0.f;
        #pragma unroll 8
        for (int cc = 0; cc < NCH; cc++) {
            float tmp = base[cc * GS_CS];
            base[cc * GS_CS] = h;
            h = fmaf(pw, h, tmp);
        }
    }
    __syncthreads();

    // ---- phase 3: re-scan from incoming state, write bf16 hi/lo ----
    float sCB[DSTATE];
    {
        const float* gp = gs + (el * NCH + c) * GS_CS;
        #pragma unroll
        for (int n = 0; n < DSTATE; n++) {
            sCB[n] = sigmoidf_(C[e * DSTATE + n]) * sigmoidf_(Bp[e * DSTATE + n]);
            g[n]   = gp[n];
        }
    }
    xm1 = xm1s; xm2 = xm2s; xm3 = xm3s;

    size_t obase = ((size_t)b * LL + t0) * EE + e;
    __nv_bfloat16* yhb = yh + obase;
    __nv_bfloat16* ylb = yl + obase;

    #pragma unroll 8
    for (int j = 0; j < CH; j++) {
        float xv = xrow[t0 + (j ^ sw)];
        float xcv = xv * w3 + xm1 * w2 + xm2 * w1 + xm3 * w0;
        xm3 = xm2; xm2 = xm1; xm1 = xv;

        float a0 = 0.f, a1 = 0.f, a2 = 0.f, a3 = 0.f;
        #pragma unroll
        for (int n = 0; n < DSTATE; n += 4) {
            g[n + 0] = fmaf(sA[n + 0], g[n + 0], xcv);
            g[n + 1] = fmaf(sA[n + 1], g[n + 1], xcv);
            g[n + 2] = fmaf(sA[n + 2], g[n + 2], xcv);
            g[n + 3] = fmaf(sA[n + 3], g[n + 3], xcv);
            a0 = fmaf(sCB[n + 0], g[n + 0], a0);
            a1 = fmaf(sCB[n + 1], g[n + 1], a1);
            a2 = fmaf(sCB[n + 2], g[n + 2], a2);
            a3 = fmaf(sCB[n + 3], g[n + 3], a3);
        }
        float v = (a0 + a1) + (a2 + a3);
        __nv_bfloat16 hv = __float2bfloat16(v);
        yhb[(size_t)j * EE] = hv;
        ylb[(size_t)j * EE] = __float2bfloat16(v - __bfloat162float(hv));
    }
}

// ---------------- launch -----------------------------------------------------
extern "C" void kernel_launch(void* const* d_in, const int* in_sizes, int n_in,
                              void* d_out, int out_size)
{
    const float* x      = (const float*)d_in[0];
    const float* gamma  = (const float*)d_in[1];
    const float* W_in   = (const float*)d_in[2];
    const float* b_in   = (const float*)d_in[3];
    const float* conv_w = (const float*)d_in[4];
    const float* A      = (const float*)d_in[5];
    const float* Bp     = (const float*)d_in[6];
    const float* C      = (const float*)d_in[7];
    const float* W_out  = (const float*)d_in[8];
    const float* b_out  = (const float*)d_in[9];
    float* out = (float*)d_out;

    float *xp;
    __nv_bfloat16 *xnh, *xnl, *winh, *winl, *wouth, *woutl, *yh, *yl;
    cudaGetSymbolAddress((void**)&xp,    g_xp);
    cudaGetSymbolAddress((void**)&xnh,   g_xnh);
    cudaGetSymbolAddress((void**)&xnl,   g_xnl);
    cudaGetSymbolAddress((void**)&winh,  g_winh);
    cudaGetSymbolAddress((void**)&winl,  g_winl);
    cudaGetSymbolAddress((void**)&wouth, g_wouth);
    cudaGetSymbolAddress((void**)&woutl, g_woutl);
    cudaGetSymbolAddress((void**)&yh,    g_yh);
    cudaGetSymbolAddress((void**)&yl,    g_yl);

    cudaFuncSetAttribute(gemm_mma_kernel<false>,
                         cudaFuncAttributeMaxDynamicSharedMemorySize, SMEM_GEMM);
    cudaFuncSetAttribute(gemm_mma_kernel<true>,
                         cudaFuncAttributeMaxDynamicSharedMemorySize, SMEM_GEMM);
    cudaFuncSetAttribute(scan_fused_kernel,
                         cudaFuncAttributeMaxDynamicSharedMemorySize, SMEM_SCAN);

    // 1. rmsnorm -> bf16 hi/lo
    rmsnorm_kernel<<<BL, 256>>>(x, gamma, xnh, xnl);

    // 1b. convert weights -> bf16 hi/lo
    convert_w_kernel<<<(2 * EE * DIM + 255) / 256, 256>>>(W_in, W_out,
                                                          winh, winl, wouth, woutl);

    // 2. in-proj (HMMA): xp = xn @ W_in^T + b_in
    {
        dim3 grid(EE / 128, BL / 128);
        gemm_mma_kernel<false><<<grid, 256, SMEM_GEMM>>>(xnh, xnl, winh, winl,
                                                         b_in, nullptr, xp, EE, DIM);
    }

    // 3. fused chunked scan (conv + local scan + combine + output)
    {
        int blocks = BB * EPB;                         // 768
        scan_fused_kernel<<<blocks, 256, SMEM_SCAN>>>(xp, A, Bp, C, conv_w, yh, yl);
    }

    // 4. out-proj + residual (HMMA): out = y @ W_out^T + b_out + x
    {
        dim3 grid(DIM / 128, BL / 128);
        gemm_mma_kernel<true><<<grid, 256, SMEM_GEMM>>>(yh, yl, wouth, woutl,
                                                        b_out, x, out, DIM, EE);
    }
}

// round 14
// speedup vs baseline: 1.2256x; 1.2256x over previous
#include <cuda_runtime.h>
#include <cuda_bf16.h>
#include <math.h>
#include <stdint.h>

#define DIM    768
#define DSTATE 16
#define DCONV  4
#define EE     1536          // expand dim
#define BB     2
#define LL     2048
#define BL     (BB*LL)       // 4096
#define EPS    1e-6f

#define CH     32            // chunk length
#define NCH    (LL/CH)       // 64 chunks

// ---------------- scratch (static device arrays; no allocations) -------------
__device__ float          g_xp  [BL * EE];              // after in-proj (fp32)
__device__ float          g_hloc[BB * NCH * DSTATE * EE];   // per-chunk final g
__device__ float          g_hin [BB * NCH * DSTATE * EE];   // per-chunk incoming g
__device__ __nv_bfloat16  g_xnh [BL * DIM];             // rmsnorm out hi
__device__ __nv_bfloat16  g_xnl [BL * DIM];             // rmsnorm out lo
__device__ __nv_bfloat16  g_winh[EE * DIM];
__device__ __nv_bfloat16  g_winl[EE * DIM];
__device__ __nv_bfloat16  g_wouth[DIM * EE];
__device__ __nv_bfloat16  g_woutl[DIM * EE];
__device__ __nv_bfloat16  g_yh  [BL * EE];              // final scan out hi
__device__ __nv_bfloat16  g_yl  [BL * EE];              // final scan out lo

__device__ __forceinline__ float sigmoidf_(float v) {
    return 1.0f / (1.0f + expf(-v));
}

__device__ __forceinline__ uint32_t smem_u32_(const void* p) {
    uint32_t a;
    asm("{ .reg .u64 t; cvta.to.shared.u64 t, %1; cvt.u32.u64 %0, t; }"
        : "=r"(a) : "l"(p));
    return a;
}

// ---------------- rmsnorm (writes bf16 hi/lo split) --------------------------
__global__ void rmsnorm_kernel(const float* __restrict__ x,
                               const float* __restrict__ gamma,
                               __nv_bfloat16* __restrict__ xnh,
                               __nv_bfloat16* __restrict__ xnl)
{
    const int row = blockIdx.x;
    const float* xr = x + (size_t)row * DIM;

    float v0 = xr[threadIdx.x];
    float v1 = xr[threadIdx.x + 256];
    float v2 = xr[threadIdx.x + 512];
    float ss = v0 * v0 + v1 * v1 + v2 * v2;

    #pragma unroll
    for (int o = 16; o > 0; o >>= 1)
        ss += __shfl_xor_sync(0xffffffffu, ss, o);

    __shared__ float warp_s[8];
    int wid = threadIdx.x >> 5, lane = threadIdx.x & 31;
    if (lane == 0) warp_s[wid] = ss;
    __syncthreads();
    if (wid == 0) {
        float t = (lane < 8) ? warp_s[lane] : 0.f;
        #pragma unroll
        for (int o = 4; o > 0; o >>= 1)
            t += __shfl_xor_sync(0xffffffffu, t, o);
        if (lane == 0) warp_s[0] = t;
    }
    __syncthreads();
    float rms = sqrtf(warp_s[0] * (1.0f / DIM));
    float inv = 1.0f / (rms + EPS);

    #pragma unroll
    for (int k = 0; k < 3; k++) {
        int i = threadIdx.x + k * 256;
        float v = (k == 0) ? v0 : (k == 1) ? v1 : v2;
        float o = gamma[i] * v * inv;
        __nv_bfloat16 h = __float2bfloat16(o);
        xnh[(size_t)row * DIM + i] = h;
        xnl[(size_t)row * DIM + i] = __float2bfloat16(o - __bfloat162float(h));
    }
}

// ---------------- weight conversion fp32 -> bf16 hi/lo -----------------------
__global__ void convert_w_kernel(const float* __restrict__ W_in,
                                 const float* __restrict__ W_out,
                                 __nv_bfloat16* __restrict__ winh,
                                 __nv_bfloat16* __restrict__ winl,
                                 __nv_bfloat16* __restrict__ wouth,
                                 __nv_bfloat16* __restrict__ woutl)
{
    const int SZ = EE * DIM;
    int idx = blockIdx.x * blockDim.x + threadIdx.x;
    if (idx >= 2 * SZ) return;
    const float* s; __nv_bfloat16 *dh, *dl; int j;
    if (idx < SZ) { s = W_in;  j = idx;      dh = winh;  dl = winl;  }
    else          { s = W_out; j = idx - SZ; dh = wouth; dl = woutl; }
    float v = s[j];
    __nv_bfloat16 h = __float2bfloat16(v);
    dh[j] = h;
    dl[j] = __float2bfloat16(v - __bfloat162float(h));
}

// ======================= HMMA (mma.sync) GEMM ================================
// C[M,N] = A[M,K] * B[N,K]^T + bias (+resid), A/B given as bf16 hi/lo pairs;
// 3 products: Ah*Bh + Ah*Bl + Al*Bh (fp32 accumulate).
// CTA tile 128x128x16, 256 threads, 8 warps (2x4), warp tile 64x32.
// 4-stage cp.async pipeline, ONE sync per iteration, 2 CTAs/SM.

#define BKT    16
#define PADR   24                      // bf16 per row (16 data + 8 pad) -> 48B rows
#define PLANE  (128 * PADR)            // 3072 bf16 per plane
#define STAGE  (4 * PLANE)             // Ah, Al, Bh, Bl -> 12288 bf16 (24576 B)
#define NSTG   4
#define SMEM_GEMM (NSTG * STAGE * 2)   // 98304 bytes

__device__ __forceinline__ void mma16816(float* d, const uint32_t* a, const uint32_t* b) {
    asm volatile(
        "mma.sync.aligned.m16n8k16.row.col.f32.bf16.bf16.f32 "
        "{%0,%1,%2,%3}, {%4,%5,%6,%7}, {%8,%9}, {%0,%1,%2,%3};"
        : "+f"(d[0]), "+f"(d[1]), "+f"(d[2]), "+f"(d[3])
        : "r"(a[0]), "r"(a[1]), "r"(a[2]), "r"(a[3]), "r"(b[0]), "r"(b[1]));
}

__device__ __forceinline__ void ldsm4(uint32_t* r, uint32_t addr) {
    asm volatile("ldmatrix.sync.aligned.m8n8.x4.shared.b16 {%0,%1,%2,%3}, [%4];"
                 : "=r"(r[0]), "=r"(r[1]), "=r"(r[2]), "=r"(r[3]) : "r"(addr));
}

#define CP_ASYNC16(s, g) asm volatile("cp.async.cg.shared.global [%0], [%1], 16;" :: "r"(s), "l"(g))
#define CP_COMMIT()      asm volatile("cp.async.commit_group;")
#define CP_WAIT2()       asm volatile("cp.async.wait_group 2;")

template<bool RESID>
__global__ __launch_bounds__(256, 2)
void gemm_mma_kernel(const __nv_bfloat16* __restrict__ Ah,
                     const __nv_bfloat16* __restrict__ Al,
                     const __nv_bfloat16* __restrict__ Bh,
                     const __nv_bfloat16* __restrict__ Bl,
                     const float* __restrict__ bias,
                     const float* __restrict__ resid,
                     float* __restrict__ Cout,
                     int N, int K)
{
    extern __shared__ __nv_bfloat16 sm[];       // 98304 bytes dynamic
    const uint32_t sm32 = smem_u32_(sm);
    const int tid  = threadIdx.x;
    const int wid  = tid >> 5, lane = tid & 31;
    const int g    = lane >> 2;
    const int t2   = (lane & 3) * 2;
    const int brow = blockIdx.y * 128, bcol = blockIdx.x * 128;
    const int warp_m = (wid >> 2) * 64;
    const int warp_n = (wid & 3) * 32;

    const __nv_bfloat16* gptr[4] = { Ah, Al, Bh, Bl };

    const int arow  = (lane & 7) + 8 * ((lane >> 3) & 1);
    const int akofs = 8 * (lane >> 4);
    const uint32_t a_off = (uint32_t)((warp_m + arow) * PADR + akofs) * 2;
    const int browl = (lane & 7) + 8 * (lane >> 4);
    const int bkofs = 8 * ((lane >> 3) & 1);
    const uint32_t b_off = (uint32_t)((warp_n + browl) * PADR + bkofs) * 2;

    float acc[4][4][4];
    #pragma unroll
    for (int mt = 0; mt < 4; mt++)
        #pragma unroll
        for (int nt = 0; nt < 4; nt++)
            #pragma unroll
            for (int q = 0; q < 4; q++) acc[mt][nt][q] = 0.f;

    // stage loader: 4 planes x 128 rows x 32B data; 1024 16B-chunks, 4/thread
    auto issue = [&](int st, int kt) {
        uint32_t sb = sm32 + (uint32_t)st * STAGE * 2;
        #pragma unroll
        for (int q = 0; q < 4; q++) {
            int ch = tid + q * 256;              // 0..1023
            int p  = ch >> 8;                    // plane 0..3
            int rc = ch & 255;
            int r  = rc >> 1;                    // row 0..127
            int c  = (rc & 1) * 8;               // bf16 col 0 or 8
            int rbase = (p < 2) ? brow : bcol;
            uint32_t sa = sb + (uint32_t)(p * PLANE + r * PADR + c) * 2;
            const __nv_bfloat16* ga = gptr[p] + (size_t)(rbase + r) * K + kt + c;
            CP_ASYNC16(sa, ga);
        }
        CP_COMMIT();
    };

    const int NK = K / BKT;
    issue(0, 0);
    issue(1, BKT);
    issue(2, 2 * BKT);

    for (int i = 0; i < NK; i++) {
        CP_WAIT2();                  // stage i's group complete (>=3 commits deep)
        __syncthreads();

        if (i + 3 < NK) issue((i + 3) & 3, (i + 3) * BKT);
        else            CP_COMMIT(); // keep commit depth so CP_WAIT2 stays valid

        const uint32_t sbase = sm32 + (uint32_t)(i & 3) * STAGE * 2;

        uint32_t ah[4][4], al[4][4], bh[2][4], bl[2][4];
        #pragma unroll
        for (int mt = 0; mt < 4; mt++) {
            uint32_t ad = sbase + a_off + (uint32_t)(mt * 16 * PADR) * 2;
            ldsm4(ah[mt], ad);
            ldsm4(al[mt], ad + (uint32_t)PLANE * 2);
        }
        #pragma unroll
        for (int ntp = 0; ntp < 2; ntp++) {
            uint32_t bd = sbase + b_off + (uint32_t)((2 * PLANE) + ntp * 16 * PADR) * 2;
            ldsm4(bh[ntp], bd);
            ldsm4(bl[ntp], bd + (uint32_t)PLANE * 2);
        }

        #pragma unroll
        for (int mt = 0; mt < 4; mt++)
            #pragma unroll
            for (int nt = 0; nt < 4; nt++) {
                const uint32_t* fh = &bh[nt >> 1][(nt & 1) * 2];
                const uint32_t* fl = &bl[nt >> 1][(nt & 1) * 2];
                mma16816(acc[mt][nt], ah[mt], fh);
                mma16816(acc[mt][nt], ah[mt], fl);
                mma16816(acc[mt][nt], al[mt], fh);
            }
    }

    #pragma unroll
    for (int mt = 0; mt < 4; mt++) {
        int r0 = brow + warp_m + mt * 16 + g;
        #pragma unroll
        for (int nt = 0; nt < 4; nt++) {
            int c = bcol + warp_n + nt * 8 + t2;
            float2 bv = *(const float2*)&bias[c];
            float2 o0, o1;
            o0.x = acc[mt][nt][0] + bv.x;
            o0.y = acc[mt][nt][1] + bv.y;
            o1.x = acc[mt][nt][2] + bv.x;
            o1.y = acc[mt][nt][3] + bv.y;
            if (RESID) {
                float2 rv0 = *(const float2*)&resid[(size_t)r0 * N + c];
                float2 rv1 = *(const float2*)&resid[(size_t)(r0 + 8) * N + c];
                o0.x += rv0.x; o0.y += rv0.y;
                o1.x += rv1.x; o1.y += rv1.y;
            }
            *(float2*)&Cout[(size_t)r0 * N + c]       = o0;
            *(float2*)&Cout[(size_t)(r0 + 8) * N + c] = o1;
        }
    }
}

// ---------------- K1: per-chunk final g-states (conv fused) ------------------
__global__ __launch_bounds__(256)
void scan_state_kernel(const float* __restrict__ xp,
                       const float* __restrict__ A,
                       const float* __restrict__ convw,
                       float* __restrict__ hloc)
{
    int tid = blockIdx.x * blockDim.x + threadIdx.x;   // b*NCH*EE + c*EE + e
    int e  = tid % EE;
    int bc = tid / EE;
    int c  = bc % NCH;
    int b  = bc / NCH;

    float sA[DSTATE], g[DSTATE];
    #pragma unroll
    for (int n = 0; n < DSTATE; n++) {
        sA[n] = sigmoidf_(A[e * DSTATE + n]);
        g[n] = 0.f;
    }
    float w0 = convw[e * 4 + 0];
    float w1 = convw[e * 4 + 1];
    float w2 = convw[e * 4 + 2];
    float w3 = convw[e * 4 + 3];

    const int t0 = c * CH;
    const float* xb = xp + (size_t)b * LL * EE + e;
    float xm1 = (t0 >= 1) ? xb[(size_t)(t0 - 1) * EE] : 0.f;
    float xm2 = (t0 >= 2) ? xb[(size_t)(t0 - 2) * EE] : 0.f;
    float xm3 = (t0 >= 3) ? xb[(size_t)(t0 - 3) * EE] : 0.f;

    const float* xq = xb + (size_t)t0 * EE;

    #pragma unroll
    for (int tb = 0; tb < CH; tb += 8) {
        float xv[8];
        #pragma unroll
        for (int j = 0; j < 8; j++)
            xv[j] = xq[(size_t)(tb + j) * EE];

        #pragma unroll
        for (int j = 0; j < 8; j++) {
            float xcv = xv[j] * w3 + xm1 * w2 + xm2 * w1 + xm3 * w0;
            xm3 = xm2; xm2 = xm1; xm1 = xv[j];
            #pragma unroll
            for (int n = 0; n < DSTATE; n++)
                g[n] = fmaf(sA[n], g[n], xcv);
        }
    }

    float* hp = hloc + (((size_t)b * NCH + c) * DSTATE) * EE + e;
    #pragma unroll
    for (int n = 0; n < DSTATE; n++)
        hp[(size_t)n * EE] = g[n];
}

// ---------------- K2: combine chunk g-states sequentially --------------------
__global__ void chunk_combine_kernel(const float* __restrict__ hloc,
                                     const float* __restrict__ A,
                                     float* __restrict__ hin)
{
    int tid = blockIdx.x * blockDim.x + threadIdx.x;   // b*DSTATE*EE + n*EE + e
    int e  = tid % EE;
    int bn = tid / EE;
    int n  = bn % DSTATE;
    int b  = bn / DSTATE;

    float sA = sigmoidf_(A[e * DSTATE + n]);
    float pw = sA;
    #pragma unroll
    for (int i = 0; i < 5; i++) pw *= pw;              // sA^32 (CH=32)

    size_t base = ((size_t)b * NCH * DSTATE + n) * EE + e;
    const size_t cstride = (size_t)DSTATE * EE;

    float h = 0.f;
    #pragma unroll
    for (int c = 0; c < NCH; c++) {
        hin[base + c * cstride] = h;
        h = fmaf(pw, h, hloc[base + c * cstride]);
    }
}

// ---------------- K3: full g-scan from hin, y = sum sCB*g, bf16 split --------
__global__ __launch_bounds__(256)
void scan_out_kernel(const float* __restrict__ xp,
                     const float* __restrict__ hin,
                     const float* __restrict__ A,
                     const float* __restrict__ Bp,
                     const float* __restrict__ C,
                     const float* __restrict__ convw,
                     __nv_bfloat16* __restrict__ yh,
                     __nv_bfloat16* __restrict__ yl)
{
    int tid = blockIdx.x * blockDim.x + threadIdx.x;   // b*NCH*EE + c*EE + e
    int e  = tid % EE;
    int bc = tid / EE;
    int c  = bc % NCH;
    int b  = bc / NCH;

    float sA[DSTATE], sCB[DSTATE], g[DSTATE];
    const float* hp = hin + (((size_t)b * NCH + c) * DSTATE) * EE + e;
    #pragma unroll
    for (int n = 0; n < DSTATE; n++) {
        sA[n]  = sigmoidf_(A[e * DSTATE + n]);
        sCB[n] = sigmoidf_(C[e * DSTATE + n]) * sigmoidf_(Bp[e * DSTATE + n]);
        g[n]   = (c > 0) ? hp[(size_t)n * EE] : 0.f;
    }
    float w0 = convw[e * 4 + 0];
    float w1 = convw[e * 4 + 1];
    float w2 = convw[e * 4 + 2];
    float w3 = convw[e * 4 + 3];

    const int t0 = c * CH;
    const float* xb = xp + (size_t)b * LL * EE + e;
    float xm1 = (t0 >= 1) ? xb[(size_t)(t0 - 1) * EE] : 0.f;
    float xm2 = (t0 >= 2) ? xb[(size_t)(t0 - 2) * EE] : 0.f;
    float xm3 = (t0 >= 3) ? xb[(size_t)(t0 - 3) * EE] : 0.f;

    const float* xq = xb + (size_t)t0 * EE;
    size_t obase = ((size_t)b * LL + t0) * EE + e;
    __nv_bfloat16* yhb = yh + obase;
    __nv_bfloat16* ylb = yl + obase;

    #pragma unroll
    for (int tb = 0; tb < CH; tb += 8) {
        float xv[8];
        #pragma unroll
        for (int j = 0; j < 8; j++)
            xv[j] = xq[(size_t)(tb + j) * EE];

        #pragma unroll
        for (int j = 0; j < 8; j++) {
            float xcv = xv[j] * w3 + xm1 * w2 + xm2 * w1 + xm3 * w0;
            xm3 = xm2; xm2 = xm1; xm1 = xv[j];

            float a0 = 0.f, a1 = 0.f, a2 = 0.f, a3 = 0.f;
            #pragma unroll
            for (int n = 0; n < DSTATE; n += 4) {
                g[n + 0] = fmaf(sA[n + 0], g[n + 0], xcv);
                g[n + 1] = fmaf(sA[n + 1], g[n + 1], xcv);
                g[n + 2] = fmaf(sA[n + 2], g[n + 2], xcv);
                g[n + 3] = fmaf(sA[n + 3], g[n + 3], xcv);
                a0 = fmaf(sCB[n + 0], g[n + 0], a0);
                a1 = fmaf(sCB[n + 1], g[n + 1], a1);
                a2 = fmaf(sCB[n + 2], g[n + 2], a2);
                a3 = fmaf(sCB[n + 3], g[n + 3], a3);
            }
            float v = (a0 + a1) + (a2 + a3);
            __nv_bfloat16 hv = __float2bfloat16(v);
            yhb[(size_t)(tb + j) * EE] = hv;
            ylb[(size_t)(tb + j) * EE] = __float2bfloat16(v - __bfloat162float(hv));
        }
    }
}

// ---------------- launch -----------------------------------------------------
extern "C" void kernel_launch(void* const* d_in, const int* in_sizes, int n_in,
                              void* d_out, int out_size)
{
    const float* x      = (const float*)d_in[0];
    const float* gamma  = (const float*)d_in[1];
    const float* W_in   = (const float*)d_in[2];
    const float* b_in   = (const float*)d_in[3];
    const float* conv_w = (const float*)d_in[4];
    const float* A      = (const float*)d_in[5];
    const float* Bp     = (const float*)d_in[6];
    const float* C      = (const float*)d_in[7];
    const float* W_out  = (const float*)d_in[8];
    const float* b_out  = (const float*)d_in[9];
    float* out = (float*)d_out;

    float *xp, *hloc, *hin;
    __nv_bfloat16 *xnh, *xnl, *winh, *winl, *wouth, *woutl, *yh, *yl;
    cudaGetSymbolAddress((void**)&xp,    g_xp);
    cudaGetSymbolAddress((void**)&hloc,  g_hloc);
    cudaGetSymbolAddress((void**)&hin,   g_hin);
    cudaGetSymbolAddress((void**)&xnh,   g_xnh);
    cudaGetSymbolAddress((void**)&xnl,   g_xnl);
    cudaGetSymbolAddress((void**)&winh,  g_winh);
    cudaGetSymbolAddress((void**)&winl,  g_winl);
    cudaGetSymbolAddress((void**)&wouth, g_wouth);
    cudaGetSymbolAddress((void**)&woutl, g_woutl);
    cudaGetSymbolAddress((void**)&yh,    g_yh);
    cudaGetSymbolAddress((void**)&yl,    g_yl);

    // idempotent, capture-safe, no static state
    cudaFuncSetAttribute(gemm_mma_kernel<false>,
                         cudaFuncAttributeMaxDynamicSharedMemorySize, SMEM_GEMM);
    cudaFuncSetAttribute(gemm_mma_kernel<true>,
                         cudaFuncAttributeMaxDynamicSharedMemorySize, SMEM_GEMM);

    // 1. rmsnorm -> bf16 hi/lo
    rmsnorm_kernel<<<BL, 256>>>(x, gamma, xnh, xnl);

    // 1b. convert weights -> bf16 hi/lo
    convert_w_kernel<<<(2 * EE * DIM + 255) / 256, 256>>>(W_in, W_out,
                                                          winh, winl, wouth, woutl);

    // 2. in-proj (HMMA): xp = xn @ W_in^T + b_in
    {
        dim3 grid(EE / 128, BL / 128);
        gemm_mma_kernel<false><<<grid, 256, SMEM_GEMM>>>(xnh, xnl, winh, winl,
                                                         b_in, nullptr, xp, EE, DIM);
    }

    // 3. chunked g-scan (conv fused)
    {
        int threads = BB * NCH * EE;                   // 196608
        scan_state_kernel<<<threads / 256, 256>>>(xp, A, conv_w, hloc);
    }
    {
        int threads = BB * DSTATE * EE;                // 49152
        chunk_combine_kernel<<<threads / 256, 256>>>(hloc, A, hin);
    }
    {
        int threads = BB * NCH * EE;
        scan_out_kernel<<<threads / 256, 256>>>(xp, hin, A, Bp, C, conv_w, yh, yl);
    }

    // 4. out-proj + residual (HMMA): out = y @ W_out^T + b_out + x
    {
        dim3 grid(DIM / 128, BL / 128);
        gemm_mma_kernel<true><<<grid, 256, SMEM_GEMM>>>(yh, yl, wouth, woutl,
                                                        b_out, x, out, DIM, EE);
    }
}

// round 15
// speedup vs baseline: 1.3913x; 1.1351x over previous
#include <cuda_runtime.h>
#include <cuda_bf16.h>
#include <math.h>
#include <stdint.h>

#define DIM    768
#define DSTATE 16
#define DCONV  4
#define EE     1536          // expand dim
#define BB     2
#define LL     2048
#define BL     (BB*LL)       // 4096
#define EPS    1e-6f

#define CH     32            // chunk length
#define NCH    (LL/CH)       // 64 chunks

// ---------------- scratch (static device arrays; no allocations) -------------
__device__ float          g_xp  [BL * EE];              // after in-proj (fp32)
__device__ float          g_hloc[BB * NCH * DSTATE * EE];   // per-chunk final g
__device__ float          g_hin [BB * NCH * DSTATE * EE];   // per-chunk incoming g
__device__ __nv_bfloat16  g_xnh [BL * DIM];             // rmsnorm out hi
__device__ __nv_bfloat16  g_xnl [BL * DIM];             // rmsnorm out lo
__device__ __nv_bfloat16  g_winh[EE * DIM];
__device__ __nv_bfloat16  g_winl[EE * DIM];
__device__ __nv_bfloat16  g_wouth[DIM * EE];
__device__ __nv_bfloat16  g_woutl[DIM * EE];
__device__ __nv_bfloat16  g_yh  [BL * EE];              // final scan out hi
__device__ __nv_bfloat16  g_yl  [BL * EE];              // final scan out lo

__device__ __forceinline__ float sigmoidf_(float v) {
    return 1.0f / (1.0f + expf(-v));
}

__device__ __forceinline__ uint32_t smem_u32_(const void* p) {
    uint32_t a;
    asm("{ .reg .u64 t; cvta.to.shared.u64 t, %1; cvt.u32.u64 %0, t; }"
        : "=r"(a) : "l"(p));
    return a;
}

// ---------------- rmsnorm (writes bf16 hi/lo split) --------------------------
__global__ void rmsnorm_kernel(const float* __restrict__ x,
                               const float* __restrict__ gamma,
                               __nv_bfloat16* __restrict__ xnh,
                               __nv_bfloat16* __restrict__ xnl)
{
    const int row = blockIdx.x;
    const float* xr = x + (size_t)row * DIM;

    float v0 = xr[threadIdx.x];
    float v1 = xr[threadIdx.x + 256];
    float v2 = xr[threadIdx.x + 512];
    float ss = v0 * v0 + v1 * v1 + v2 * v2;

    #pragma unroll
    for (int o = 16; o > 0; o >>= 1)
        ss += __shfl_xor_sync(0xffffffffu, ss, o);

    __shared__ float warp_s[8];
    int wid = threadIdx.x >> 5, lane = threadIdx.x & 31;
    if (lane == 0) warp_s[wid] = ss;
    __syncthreads();
    if (wid == 0) {
        float t = (lane < 8) ? warp_s[lane] : 0.f;
        #pragma unroll
        for (int o = 4; o > 0; o >>= 1)
            t += __shfl_xor_sync(0xffffffffu, t, o);
        if (lane == 0) warp_s[0] = t;
    }
    __syncthreads();
    float rms = sqrtf(warp_s[0] * (1.0f / DIM));
    float inv = 1.0f / (rms + EPS);

    #pragma unroll
    for (int k = 0; k < 3; k++) {
        int i = threadIdx.x + k * 256;
        float v = (k == 0) ? v0 : (k == 1) ? v1 : v2;
        float o = gamma[i] * v * inv;
        __nv_bfloat16 h = __float2bfloat16(o);
        xnh[(size_t)row * DIM + i] = h;
        xnl[(size_t)row * DIM + i] = __float2bfloat16(o - __bfloat162float(h));
    }
}

// ---------------- weight conversion fp32 -> bf16 hi/lo -----------------------
__global__ void convert_w_kernel(const float* __restrict__ W_in,
                                 const float* __restrict__ W_out,
                                 __nv_bfloat16* __restrict__ winh,
                                 __nv_bfloat16* __restrict__ winl,
                                 __nv_bfloat16* __restrict__ wouth,
                                 __nv_bfloat16* __restrict__ woutl)
{
    const int SZ = EE * DIM;
    int idx = blockIdx.x * blockDim.x + threadIdx.x;
    if (idx >= 2 * SZ) return;
    const float* s; __nv_bfloat16 *dh, *dl; int j;
    if (idx < SZ) { s = W_in;  j = idx;      dh = winh;  dl = winl;  }
    else          { s = W_out; j = idx - SZ; dh = wouth; dl = woutl; }
    float v = s[j];
    __nv_bfloat16 h = __float2bfloat16(v);
    dh[j] = h;
    dl[j] = __float2bfloat16(v - __bfloat162float(h));
}

// ======================= HMMA (mma.sync) GEMM ================================
// C[M,N] = A[M,K] * B[N,K]^T + bias (+resid), A/B given as bf16 hi/lo pairs;
// 3 products: Ah*Bh + Ah*Bl + Al*Bh (fp32 accumulate).
// CTA tile 64x128x32, 256 threads, 8 warps (2x4), warp tile 32x32.
// 16B cp.async, 2-stage, 61440B smem -> 3 CTAs/SM (load balance).

#define BKT    32
#define PADR   40                      // bf16 per row (32 data + 8 pad) -> 80B rows
#define APLANE (64 * PADR)             // 2560 bf16 (A planes: 64 rows)
#define BPLANE (128 * PADR)            // 5120 bf16 (B planes: 128 rows)
#define STAGE  (2 * APLANE + 2 * BPLANE)   // 15360 bf16 = 30720 B
#define SMEM_GEMM (2 * STAGE * 2)      // 61440 bytes

__device__ __forceinline__ void mma16816(float* d, const uint32_t* a, const uint32_t* b) {
    asm volatile(
        "mma.sync.aligned.m16n8k16.row.col.f32.bf16.bf16.f32 "
        "{%0,%1,%2,%3}, {%4,%5,%6,%7}, {%8,%9}, {%0,%1,%2,%3};"
        : "+f"(d[0]), "+f"(d[1]), "+f"(d[2]), "+f"(d[3])
        : "r"(a[0]), "r"(a[1]), "r"(a[2]), "r"(a[3]), "r"(b[0]), "r"(b[1]));
}

__device__ __forceinline__ void ldsm4(uint32_t* r, uint32_t addr) {
    asm volatile("ldmatrix.sync.aligned.m8n8.x4.shared.b16 {%0,%1,%2,%3}, [%4];"
                 : "=r"(r[0]), "=r"(r[1]), "=r"(r[2]), "=r"(r[3]) : "r"(addr));
}

#define CP_ASYNC16(s, g) asm volatile("cp.async.cg.shared.global [%0], [%1], 16;" :: "r"(s), "l"(g))
#define CP_COMMIT()      asm volatile("cp.async.commit_group;")
#define CP_WAIT1()       asm volatile("cp.async.wait_group 1;")

template<bool RESID>
__global__ __launch_bounds__(256, 3)
void gemm_mma_kernel(const __nv_bfloat16* __restrict__ Ah,
                     const __nv_bfloat16* __restrict__ Al,
                     const __nv_bfloat16* __restrict__ Bh,
                     const __nv_bfloat16* __restrict__ Bl,
                     const float* __restrict__ bias,
                     const float* __restrict__ resid,
                     float* __restrict__ Cout,
                     int N, int K)
{
    extern __shared__ __nv_bfloat16 sm[];       // 61440 bytes dynamic
    const uint32_t sm32 = smem_u32_(sm);
    const int tid  = threadIdx.x;
    const int wid  = tid >> 5, lane = tid & 31;
    const int g    = lane >> 2;
    const int t2   = (lane & 3) * 2;
    const int brow = blockIdx.y * 64, bcol = blockIdx.x * 128;
    const int warp_m = (wid >> 2) * 32;   // 0 or 32
    const int warp_n = (wid & 3) * 32;    // 0,32,64,96

    const __nv_bfloat16* gptr[4] = { Ah, Al, Bh, Bl };

    // per-lane ldmatrix byte offsets (within plane)
    const int arow  = (lane & 7) + 8 * ((lane >> 3) & 1);
    const int akofs = 8 * (lane >> 4);
    const uint32_t a_off = (uint32_t)((warp_m + arow) * PADR + akofs) * 2;
    const int browl = (lane & 7) + 8 * (lane >> 4);
    const int bkofs = 8 * ((lane >> 3) & 1);
    const uint32_t b_off = (uint32_t)((warp_n + browl) * PADR + bkofs) * 2;

    float acc[2][4][4];
    #pragma unroll
    for (int mt = 0; mt < 2; mt++)
        #pragma unroll
        for (int nt = 0; nt < 4; nt++)
            #pragma unroll
            for (int q = 0; q < 4; q++) acc[mt][nt][q] = 0.f;

    // stage loader: A planes 64 rows, B planes 128 rows, 64B data/row.
    // 1536 16B-chunks total -> 6 per thread.
    auto issue = [&](int st, int kt) {
        uint32_t sb = sm32 + (uint32_t)st * STAGE * 2;
        #pragma unroll
        for (int q = 0; q < 6; q++) {
            int ch = tid + q * 256;              // 0..1535
            int r, rbase;
            uint32_t pofs;
            const __nv_bfloat16* gp;
            if (ch < 512) {                      // Ah / Al: 256 chunks each
                int pa = ch >> 8;                // 0=Ah 1=Al
                int rc = ch & 255;
                r = rc >> 2;
                pofs = (uint32_t)(pa * APLANE);
                gp = gptr[pa];
                rbase = brow;
            } else {                             // Bh / Bl: 512 chunks each
                int cb = ch - 512;
                int pb = cb >> 9;                // 0=Bh 1=Bl
                int rc = cb & 511;
                r = rc >> 2;
                pofs = (uint32_t)(2 * APLANE + pb * BPLANE);
                gp = gptr[2 + pb];
                rbase = bcol;
            }
            int c = (ch & 3) * 8;                // bf16 col 0,8,16,24
            uint32_t sa = sb + (pofs + (uint32_t)(r * PADR + c)) * 2;
            const __nv_bfloat16* ga = gp + (size_t)(rbase + r) * K + kt + c;
            CP_ASYNC16(sa, ga);
        }
        CP_COMMIT();
    };

    const int NK = K / BKT;
    issue(0, 0);
    issue(1, BKT);
    CP_WAIT1();
    __syncthreads();

    for (int i = 0; i < NK; i++) {
        const int st = i & 1;
        const uint32_t sbase = sm32 + (uint32_t)st * STAGE * 2;

        #pragma unroll
        for (int kk = 0; kk < BKT; kk += 16) {
            const uint32_t kb = (uint32_t)kk * 2;
            uint32_t ah[2][4], al[2][4], bh[2][4], bl[2][4];
            #pragma unroll
            for (int mt = 0; mt < 2; mt++) {
                uint32_t ad = sbase + a_off + (uint32_t)(mt * 16 * PADR) * 2 + kb;
                ldsm4(ah[mt], ad);
                ldsm4(al[mt], ad + (uint32_t)APLANE * 2);
            }
            #pragma unroll
            for (int ntp = 0; ntp < 2; ntp++) {
                uint32_t bd = sbase + b_off
                            + (uint32_t)(2 * APLANE + ntp * 16 * PADR) * 2 + kb;
                ldsm4(bh[ntp], bd);
                ldsm4(bl[ntp], bd + (uint32_t)BPLANE * 2);
            }

            #pragma unroll
            for (int mt = 0; mt < 2; mt++)
                #pragma unroll
                for (int nt = 0; nt < 4; nt++) {
                    const uint32_t* fh = &bh[nt >> 1][(nt & 1) * 2];
                    const uint32_t* fl = &bl[nt >> 1][(nt & 1) * 2];
                    mma16816(acc[mt][nt], ah[mt], fh);
                    mma16816(acc[mt][nt], ah[mt], fl);
                    mma16816(acc[mt][nt], al[mt], fh);
                }
        }

        __syncthreads();
        if (i + 2 < NK) issue(st, (i + 2) * BKT);
        else            CP_COMMIT();
        CP_WAIT1();
        __syncthreads();
    }

    #pragma unroll
    for (int mt = 0; mt < 2; mt++) {
        int r0 = brow + warp_m + mt * 16 + g;
        #pragma unroll
        for (int nt = 0; nt < 4; nt++) {
            int c = bcol + warp_n + nt * 8 + t2;
            float2 bv = *(const float2*)&bias[c];
            float2 o0, o1;
            o0.x = acc[mt][nt][0] + bv.x;
            o0.y = acc[mt][nt][1] + bv.y;
            o1.x = acc[mt][nt][2] + bv.x;
            o1.y = acc[mt][nt][3] + bv.y;
            if (RESID) {
                float2 rv0 = *(const float2*)&resid[(size_t)r0 * N + c];
                float2 rv1 = *(const float2*)&resid[(size_t)(r0 + 8) * N + c];
                o0.x += rv0.x; o0.y += rv0.y;
                o1.x += rv1.x; o1.y += rv1.y;
            }
            *(float2*)&Cout[(size_t)r0 * N + c]       = o0;
            *(float2*)&Cout[(size_t)(r0 + 8) * N + c] = o1;
        }
    }
}

// ---------------- K1: per-chunk final g-states (conv fused) ------------------
__global__ __launch_bounds__(256)
void scan_state_kernel(const float* __restrict__ xp,
                       const float* __restrict__ A,
                       const float* __restrict__ convw,
                       float* __restrict__ hloc)
{
    int tid = blockIdx.x * blockDim.x + threadIdx.x;   // b*NCH*EE + c*EE + e
    int e  = tid % EE;
    int bc = tid / EE;
    int c  = bc % NCH;
    int b  = bc / NCH;

    float sA[DSTATE], g[DSTATE];
    #pragma unroll
    for (int n = 0; n < DSTATE; n++) {
        sA[n] = sigmoidf_(A[e * DSTATE + n]);
        g[n] = 0.f;
    }
    float w0 = convw[e * 4 + 0];
    float w1 = convw[e * 4 + 1];
    float w2 = convw[e * 4 + 2];
    float w3 = convw[e * 4 + 3];

    const int t0 = c * CH;
    const float* xb = xp + (size_t)b * LL * EE + e;
    float xm1 = (t0 >= 1) ? xb[(size_t)(t0 - 1) * EE] : 0.f;
    float xm2 = (t0 >= 2) ? xb[(size_t)(t0 - 2) * EE] : 0.f;
    float xm3 = (t0 >= 3) ? xb[(size_t)(t0 - 3) * EE] : 0.f;

    const float* xq = xb + (size_t)t0 * EE;

    #pragma unroll
    for (int tb = 0; tb < CH; tb += 8) {
        float xv[8];
        #pragma unroll
        for (int j = 0; j < 8; j++)
            xv[j] = xq[(size_t)(tb + j) * EE];

        #pragma unroll
        for (int j = 0; j < 8; j++) {
            float xcv = xv[j] * w3 + xm1 * w2 + xm2 * w1 + xm3 * w0;
            xm3 = xm2; xm2 = xm1; xm1 = xv[j];
            #pragma unroll
            for (int n = 0; n < DSTATE; n++)
                g[n] = fmaf(sA[n], g[n], xcv);
        }
    }

    float* hp = hloc + (((size_t)b * NCH + c) * DSTATE) * EE + e;
    #pragma unroll
    for (int n = 0; n < DSTATE; n++)
        hp[(size_t)n * EE] = g[n];
}

// ---------------- K2: combine chunk g-states sequentially --------------------
__global__ void chunk_combine_kernel(const float* __restrict__ hloc,
                                     const float* __restrict__ A,
                                     float* __restrict__ hin)
{
    int tid = blockIdx.x * blockDim.x + threadIdx.x;   // b*DSTATE*EE + n*EE + e
    int e  = tid % EE;
    int bn = tid / EE;
    int n  = bn % DSTATE;
    int b  = bn / DSTATE;

    float sA = sigmoidf_(A[e * DSTATE + n]);
    float pw = sA;
    #pragma unroll
    for (int i = 0; i < 5; i++) pw *= pw;              // sA^32 (CH=32)

    size_t base = ((size_t)b * NCH * DSTATE + n) * EE + e;
    const size_t cstride = (size_t)DSTATE * EE;

    float h = 0.f;
    #pragma unroll
    for (int c = 0; c < NCH; c++) {
        hin[base + c * cstride] = h;
        h = fmaf(pw, h, hloc[base + c * cstride]);
    }
}

// ---------------- K3: full g-scan from hin, y = sum sCB*g, bf16 split --------
__global__ __launch_bounds__(256)
void scan_out_kernel(const float* __restrict__ xp,
                     const float* __restrict__ hin,
                     const float* __restrict__ A,
                     const float* __restrict__ Bp,
                     const float* __restrict__ C,
                     const float* __restrict__ convw,
                     __nv_bfloat16* __restrict__ yh,
                     __nv_bfloat16* __restrict__ yl)
{
    int tid = blockIdx.x * blockDim.x + threadIdx.x;   // b*NCH*EE + c*EE + e
    int e  = tid % EE;
    int bc = tid / EE;
    int c  = bc % NCH;
    int b  = bc / NCH;

    float sA[DSTATE], sCB[DSTATE], g[DSTATE];
    const float* hp = hin + (((size_t)b * NCH + c) * DSTATE) * EE + e;
    #pragma unroll
    for (int n = 0; n < DSTATE; n++) {
        sA[n]  = sigmoidf_(A[e * DSTATE + n]);
        sCB[n] = sigmoidf_(C[e * DSTATE + n]) * sigmoidf_(Bp[e * DSTATE + n]);
        g[n]   = (c > 0) ? hp[(size_t)n * EE] : 0.f;
    }
    float w0 = convw[e * 4 + 0];
    float w1 = convw[e * 4 + 1];
    float w2 = convw[e * 4 + 2];
    float w3 = convw[e * 4 + 3];

    const int t0 = c * CH;
    const float* xb = xp + (size_t)b * LL * EE + e;
    float xm1 = (t0 >= 1) ? xb[(size_t)(t0 - 1) * EE] : 0.f;
    float xm2 = (t0 >= 2) ? xb[(size_t)(t0 - 2) * EE] : 0.f;
    float xm3 = (t0 >= 3) ? xb[(size_t)(t0 - 3) * EE] : 0.f;

    const float* xq = xb + (size_t)t0 * EE;
    size_t obase = ((size_t)b * LL + t0) * EE + e;
    __nv_bfloat16* yhb = yh + obase;
    __nv_bfloat16* ylb = yl + obase;

    #pragma unroll
    for (int tb = 0; tb < CH; tb += 8) {
        float xv[8];
        #pragma unroll
        for (int j = 0; j < 8; j++)
            xv[j] = xq[(size_t)(tb + j) * EE];

        #pragma unroll
        for (int j = 0; j < 8; j++) {
            float xcv = xv[j] * w3 + xm1 * w2 + xm2 * w1 + xm3 * w0;
            xm3 = xm2; xm2 = xm1; xm1 = xv[j];

            float a0 = 0.f, a1 = 0.f, a2 = 0.f, a3 = 0.f;
            #pragma unroll
            for (int n = 0; n < DSTATE; n += 4) {
                g[n + 0] = fmaf(sA[n + 0], g[n + 0], xcv);
                g[n + 1] = fmaf(sA[n + 1], g[n + 1], xcv);
                g[n + 2] = fmaf(sA[n + 2], g[n + 2], xcv);
                g[n + 3] = fmaf(sA[n + 3], g[n + 3], xcv);
                a0 = fmaf(sCB[n + 0], g[n + 0], a0);
                a1 = fmaf(sCB[n + 1], g[n + 1], a1);
                a2 = fmaf(sCB[n + 2], g[n + 2], a2);
                a3 = fmaf(sCB[n + 3], g[n + 3], a3);
            }
            float v = (a0 + a1) + (a2 + a3);
            __nv_bfloat16 hv = __float2bfloat16(v);
            yhb[(size_t)(tb + j) * EE] = hv;
            ylb[(size_t)(tb + j) * EE] = __float2bfloat16(v - __bfloat162float(hv));
        }
    }
}

// ---------------- launch -----------------------------------------------------
extern "C" void kernel_launch(void* const* d_in, const int* in_sizes, int n_in,
                              void* d_out, int out_size)
{
    const float* x      = (const float*)d_in[0];
    const float* gamma  = (const float*)d_in[1];
    const float* W_in   = (const float*)d_in[2];
    const float* b_in   = (const float*)d_in[3];
    const float* conv_w = (const float*)d_in[4];
    const float* A      = (const float*)d_in[5];
    const float* Bp     = (const float*)d_in[6];
    const float* C      = (const float*)d_in[7];
    const float* W_out  = (const float*)d_in[8];
    const float* b_out  = (const float*)d_in[9];
    float* out = (float*)d_out;

    float *xp, *hloc, *hin;
    __nv_bfloat16 *xnh, *xnl, *winh, *winl, *wouth, *woutl, *yh, *yl;
    cudaGetSymbolAddress((void**)&xp,    g_xp);
    cudaGetSymbolAddress((void**)&hloc,  g_hloc);
    cudaGetSymbolAddress((void**)&hin,   g_hin);
    cudaGetSymbolAddress((void**)&xnh,   g_xnh);
    cudaGetSymbolAddress((void**)&xnl,   g_xnl);
    cudaGetSymbolAddress((void**)&winh,  g_winh);
    cudaGetSymbolAddress((void**)&winl,  g_winl);
    cudaGetSymbolAddress((void**)&wouth, g_wouth);
    cudaGetSymbolAddress((void**)&woutl, g_woutl);
    cudaGetSymbolAddress((void**)&yh,    g_yh);
    cudaGetSymbolAddress((void**)&yl,    g_yl);

    // idempotent, capture-safe, no static state
    cudaFuncSetAttribute(gemm_mma_kernel<false>,
                         cudaFuncAttributeMaxDynamicSharedMemorySize, SMEM_GEMM);
    cudaFuncSetAttribute(gemm_mma_kernel<true>,
                         cudaFuncAttributeMaxDynamicSharedMemorySize, SMEM_GEMM);

    // 1. rmsnorm -> bf16 hi/lo
    rmsnorm_kernel<<<BL, 256>>>(x, gamma, xnh, xnl);

    // 1b. convert weights -> bf16 hi/lo
    convert_w_kernel<<<(2 * EE * DIM + 255) / 256, 256>>>(W_in, W_out,
                                                          winh, winl, wouth, woutl);

    // 2. in-proj (HMMA): xp = xn @ W_in^T + b_in
    {
        dim3 grid(EE / 128, BL / 64);
        gemm_mma_kernel<false><<<grid, 256, SMEM_GEMM>>>(xnh, xnl, winh, winl,
                                                         b_in, nullptr, xp, EE, DIM);
    }

    // 3. chunked g-scan (conv fused)
    {
        int threads = BB * NCH * EE;                   // 196608
        scan_state_kernel<<<threads / 256, 256>>>(xp, A, conv_w, hloc);
    }
    {
        int threads = BB * DSTATE * EE;                // 49152
        chunk_combine_kernel<<<threads / 256, 256>>>(hloc, A, hin);
    }
    {
        int threads = BB * NCH * EE;
        scan_out_kernel<<<threads / 256, 256>>>(xp, hin, A, Bp, C, conv_w, yh, yl);
    }

    // 4. out-proj + residual (HMMA): out = y @ W_out^T + b_out + x
    {
        dim3 grid(DIM / 128, BL / 64);
        gemm_mma_kernel<true><<<grid, 256, SMEM_GEMM>>>(yh, yl, wouth, woutl,
                                                        b_out, x, out, DIM, EE);
    }
}